// round 2
// baseline (speedup 1.0000x reference)
#include <cuda_runtime.h>
#include <cstdint>

#define BB   512
#define NN   256
#define NVT  32
#define HS   128
#define G3   384   // 3*HS
#define NZ   64
#define VT   16    // v-tile per thread in pass 2 (8 packed pairs)

// ---------- precomputed tables (device globals: no allocation allowed) ----------
__device__ float4 g_C[NVT * HS];    // (mr, mz, mn, tb) per (t, h)
__device__ float  g_gi[NVT * G3];   // gi[t][g] = W_ih[g][t] + b_ih[g]

// ---------- packed f32x2 helpers (sm_103a) ----------
__device__ __forceinline__ unsigned long long pack2(float x, float y) {
    unsigned long long r;
    asm("mov.b64 %0, {%1, %2};" : "=l"(r) : "f"(x), "f"(y));
    return r;
}
__device__ __forceinline__ void unpack2(unsigned long long v, float& x, float& y) {
    asm("mov.b64 {%0, %1}, %2;" : "=f"(x), "=f"(y) : "l"(v));
}
__device__ __forceinline__ void fma2(unsigned long long& d,
                                     unsigned long long a, unsigned long long b) {
    asm("fma.rn.f32x2 %0, %1, %2, %0;" : "+l"(d) : "l"(a), "l"(b));
}

__device__ __forceinline__ float fast_sigmoid(float x) {
    return __fdividef(1.f, 1.f + __expf(-x));
}
__device__ __forceinline__ float fast_tanh(float x) {
    float e = __expf(2.f * x);
    return 1.f - __fdividef(2.f, e + 1.f);
}

// ---------- kernel A: build tables ----------
__global__ void dvae_tables_kernel(const float* __restrict__ W_ih,
                                   const float* __restrict__ W_hh,
                                   const float* __restrict__ b_ih,
                                   const float* __restrict__ Wg,
                                   const float* __restrict__ bg,
                                   const float* __restrict__ Wm) {
    __shared__ float s_tbl[HS];
    int t = blockIdx.x;      // 0..31
    int g = threadIdx.x;     // 0..383
    if (g < HS) {
        float x  = Wg[g * NVT + t] + bg[g];
        float sg = __fdividef(1.f, 1.f + __expf(-x));
        float v  = sg * Wm[g * NVT + t];
        s_tbl[g] = v;
    }
    __syncthreads();
    float acc = 0.f;
    #pragma unroll 8
    for (int h = 0; h < HS; h++) acc += s_tbl[h] * W_hh[g * HS + h];
    // scatter into the interleaved coefficient table
    int h   = g & (HS - 1);
    int sel = g >> 7;            // 0:r 1:z 2:n
    float* c = (float*)&g_C[t * HS + h];
    c[sel] = acc;
    if (sel == 0) c[3] = s_tbl[h];
    g_gi[t * G3 + g] = W_ih[g * NVT + t] + b_ih[g];
}

// ---------- kernel B: per-batch histogram + GRU + heads ----------
// smem: s_C 64K + s_cnt 32K + s_type 1K + s_hg 512B
#define SMEM_BYTES (65536 + 32768 + 1024 + 512)

__global__ __launch_bounds__(256, 2)
void dvae_main_kernel(const int* __restrict__ node_types,
                      const int* __restrict__ adj,
                      const float* __restrict__ b_hh,
                      const float* __restrict__ W1, const float* __restrict__ b1,
                      const float* __restrict__ W2, const float* __restrict__ b2,
                      float* __restrict__ out) {
    extern __shared__ char smem[];
    float4* s_C   = (float4*)smem;                        // [32][128]
    float*  s_cnt = (float*)(s_C + NVT * HS);             // [32][256]
    int*    s_cnti = (int*)s_cnt;
    int*    s_type = (int*)(s_cnt + NVT * NN);            // [256]
    float*  s_hg   = (float*)(s_type + NN);               // [128]

    const int b   = blockIdx.x;
    const int tid = threadIdx.x;

    // stage coefficient table (float4 copies), types, zero counters
    {
        const float4* src = g_C;
        for (int i = tid; i < NVT * HS; i += 256) s_C[i] = src[i];
    }
    s_type[tid] = node_types[b * NN + tid];
    for (int i = tid; i < NVT * NN; i += 256) s_cnti[i] = 0;
    __syncthreads();

    // ---- pass 1: per-(v,type) predecessor histogram, MLP=8 batching ----
    {
        const int* arow = adj + (size_t)b * NN * NN + tid;  // coalesced over v=tid
        #pragma unroll 1
        for (int u0 = 0; u0 < NN; u0 += 8) {
            int a0 = __ldg(arow + (u0 + 0) * NN);
            int a1 = __ldg(arow + (u0 + 1) * NN);
            int a2 = __ldg(arow + (u0 + 2) * NN);
            int a3 = __ldg(arow + (u0 + 3) * NN);
            int a4 = __ldg(arow + (u0 + 4) * NN);
            int a5 = __ldg(arow + (u0 + 5) * NN);
            int a6 = __ldg(arow + (u0 + 6) * NN);
            int a7 = __ldg(arow + (u0 + 7) * NN);
            s_cnti[s_type[u0 + 0] * NN + tid] += a0;
            s_cnti[s_type[u0 + 1] * NN + tid] += a1;
            s_cnti[s_type[u0 + 2] * NN + tid] += a2;
            s_cnti[s_type[u0 + 3] * NN + tid] += a3;
            s_cnti[s_type[u0 + 4] * NN + tid] += a4;
            s_cnti[s_type[u0 + 5] * NN + tid] += a5;
            s_cnti[s_type[u0 + 6] * NN + tid] += a6;
            s_cnti[s_type[u0 + 7] * NN + tid] += a7;
        }
    }
    __syncthreads();
    // in-place int -> float
    for (int i = tid; i < NVT * NN; i += 256)
        s_cnti[i] = __float_as_int((float)s_cnti[i]);
    __syncthreads();

    // ---- pass 2: gh = cnt@M (+b_hh), Hpre = cnt@tbl, GRU, graph sum ----
    const int hh  = tid & 127;   // h index
    const int grp = tid >> 7;    // which v-subtile (0/1)
    const unsigned long long bhr2 = pack2(b_hh[hh],          b_hh[hh]);
    const unsigned long long bhz2 = pack2(b_hh[HS + hh],     b_hh[HS + hh]);
    const unsigned long long bhn2 = pack2(b_hh[2 * HS + hh], b_hh[2 * HS + hh]);
    float hg = 0.f;

    for (int v0 = 0; v0 < NN; v0 += 2 * VT) {
        const int vb = v0 + grp * VT;
        unsigned long long gr[VT / 2], gz[VT / 2], gn[VT / 2], hp[VT / 2];
        #pragma unroll
        for (int p = 0; p < VT / 2; p++) {
            gr[p] = bhr2; gz[p] = bhz2; gn[p] = bhn2; hp[p] = 0ull;
        }

        #pragma unroll 4
        for (int t = 0; t < NVT; t++) {
            const float4 co = s_C[t * HS + hh];                 // LDS.128
            const unsigned long long mr2 = pack2(co.x, co.x);
            const unsigned long long mz2 = pack2(co.y, co.y);
            const unsigned long long mn2 = pack2(co.z, co.z);
            const unsigned long long tb2 = pack2(co.w, co.w);
            const unsigned long long* cp =
                (const unsigned long long*)(s_cnt + t * NN + vb); // 8B-aligned
            #pragma unroll
            for (int p = 0; p < VT / 2; p++) {
                const unsigned long long c2 = cp[p];            // LDS.64 broadcast
                fma2(gr[p], c2, mr2);
                fma2(gz[p], c2, mz2);
                fma2(gn[p], c2, mn2);
                fma2(hp[p], c2, tb2);
            }
        }

        // GRU epilogue for this v-tile
        #pragma unroll
        for (int p = 0; p < VT / 2; p++) {
            float grf[2], gzf[2], gnf[2], hpf[2];
            unpack2(gr[p], grf[0], grf[1]);
            unpack2(gz[p], gzf[0], gzf[1]);
            unpack2(gn[p], gnf[0], gnf[1]);
            unpack2(hp[p], hpf[0], hpf[1]);
            #pragma unroll
            for (int q = 0; q < 2; q++) {
                const int v  = vb + 2 * p + q;
                const int tv = s_type[v];
                const float gir = __ldg(&g_gi[tv * G3 + hh]);
                const float giz = __ldg(&g_gi[tv * G3 + HS + hh]);
                const float gin = __ldg(&g_gi[tv * G3 + 2 * HS + hh]);
                float r  = fast_sigmoid(gir + grf[q]);
                float z  = fast_sigmoid(giz + gzf[q]);
                float nn = fast_tanh(gin + r * gnf[q]);
                float Hv = (1.f - z) * nn + z * hpf[q];
                if (v >= 1 && v < NN - 1) hg += Hv;   // graph state: v in [1, N-1)
            }
        }
    }

    // reduce the two v-groups into s_hg[h]
    if (grp == 0) s_hg[hh] = hg;
    __syncthreads();
    if (grp == 1) s_hg[hh] += hg;
    __syncthreads();

    // ---- heads: mu (threads 0..63), logvar (threads 64..127) ----
    if (tid < 2 * NZ) {
        const int j = tid & (NZ - 1);
        const float* W  = (tid < NZ) ? W1 : W2;
        const float* bv = (tid < NZ) ? b1 : b2;
        float acc = bv[j];
        #pragma unroll 8
        for (int h = 0; h < HS; h++) acc += s_hg[h] * W[j * HS + h];
        out[((tid < NZ) ? 0 : BB * NZ) + b * NZ + j] = acc;
    }
}

// ---------- launch ----------
extern "C" void kernel_launch(void* const* d_in, const int* in_sizes, int n_in,
                              void* d_out, int out_size) {
    const int*   node_types = (const int*)  d_in[0];
    const int*   adj        = (const int*)  d_in[1];
    const float* W_ih       = (const float*)d_in[2];
    const float* W_hh       = (const float*)d_in[3];
    const float* b_ih       = (const float*)d_in[4];
    const float* b_hh       = (const float*)d_in[5];
    const float* Wg         = (const float*)d_in[6];
    const float* bg         = (const float*)d_in[7];
    const float* Wm         = (const float*)d_in[8];
    const float* W1         = (const float*)d_in[9];
    const float* b1         = (const float*)d_in[10];
    const float* W2         = (const float*)d_in[11];
    const float* b2         = (const float*)d_in[12];
    float* out = (float*)d_out;

    cudaFuncSetAttribute(dvae_main_kernel,
                         cudaFuncAttributeMaxDynamicSharedMemorySize, SMEM_BYTES);

    dvae_tables_kernel<<<NVT, G3>>>(W_ih, W_hh, b_ih, Wg, bg, Wm);
    dvae_main_kernel<<<BB, 256, SMEM_BYTES>>>(node_types, adj, b_hh,
                                              W1, b1, W2, b2, out);
}

// round 3
// speedup vs baseline: 1.6373x; 1.6373x over previous
#include <cuda_runtime.h>
#include <cstdint>

#define BB   512
#define NN   256
#define NVT  32
#define HS   128
#define G3   384   // 3*HS
#define NZ   64
#define VT   16    // v-tile per thread group in pass 2

// ---------- device globals (no allocation allowed) ----------
__device__ float4 g_C[NVT * HS];          // (mr, mz, mn, tb) per (t, h)
__device__ float  g_gi[NVT * G3];         // gi[t][g] = W_ih[g][t] + b_ih[g]
__device__ float  g_cnt[BB * NVT * NN];   // per-batch type histogram (16 MB)

__device__ __forceinline__ float fast_sigmoid(float x) {
    return __fdividef(1.f, 1.f + __expf(-x));
}
__device__ __forceinline__ float fast_tanh(float x) {
    float e = __expf(2.f * x);
    return 1.f - __fdividef(2.f, e + 1.f);
}

// ---------- kernel A: build tables ----------
__global__ void dvae_tables_kernel(const float* __restrict__ W_ih,
                                   const float* __restrict__ W_hh,
                                   const float* __restrict__ b_ih,
                                   const float* __restrict__ Wg,
                                   const float* __restrict__ bg,
                                   const float* __restrict__ Wm) {
    __shared__ float s_tbl[HS];
    int t = blockIdx.x;      // 0..31
    int g = threadIdx.x;     // 0..383
    if (g < HS) {
        float x  = Wg[g * NVT + t] + bg[g];
        float sg = __fdividef(1.f, 1.f + __expf(-x));
        float v  = sg * Wm[g * NVT + t];
        s_tbl[g] = v;
    }
    __syncthreads();
    float acc = 0.f;
    #pragma unroll 8
    for (int h = 0; h < HS; h++) acc += s_tbl[h] * W_hh[g * HS + h];
    int h   = g & (HS - 1);
    int sel = g >> 7;            // 0:r 1:z 2:n
    float* c = (float*)&g_C[t * HS + h];
    c[sel] = acc;
    if (sel == 0) c[3] = s_tbl[h];
    g_gi[t * G3 + g] = W_ih[g * NVT + t] + b_ih[g];
}

// ---------- kernel B1: per-batch predecessor-type histogram ----------
// smem: 32KB counters + 1KB types -> ~6 CTAs/SM, all 512 CTAs resident.
__global__ __launch_bounds__(256)
void dvae_hist_kernel(const int* __restrict__ node_types,
                      const int* __restrict__ adj) {
    __shared__ int s_cnti[NVT * NN];
    __shared__ int s_type[NN];

    const int b   = blockIdx.x;
    const int tid = threadIdx.x;

    s_type[tid] = node_types[b * NN + tid];
    for (int i = tid; i < NVT * NN; i += 256) s_cnti[i] = 0;
    __syncthreads();

    const int* arow = adj + (size_t)b * NN * NN + tid;  // coalesced over v=tid
    #pragma unroll 1
    for (int u0 = 0; u0 < NN; u0 += 8) {
        // batch 8 independent loads (MLP=8) before any dependent smem RMW
        int a0 = __ldg(arow + (u0 + 0) * NN);
        int a1 = __ldg(arow + (u0 + 1) * NN);
        int a2 = __ldg(arow + (u0 + 2) * NN);
        int a3 = __ldg(arow + (u0 + 3) * NN);
        int a4 = __ldg(arow + (u0 + 4) * NN);
        int a5 = __ldg(arow + (u0 + 5) * NN);
        int a6 = __ldg(arow + (u0 + 6) * NN);
        int a7 = __ldg(arow + (u0 + 7) * NN);
        int t0 = s_type[u0 + 0], t1 = s_type[u0 + 1];
        int t2 = s_type[u0 + 2], t3 = s_type[u0 + 3];
        int t4 = s_type[u0 + 4], t5 = s_type[u0 + 5];
        int t6 = s_type[u0 + 6], t7 = s_type[u0 + 7];
        s_cnti[t0 * NN + tid] += a0;
        s_cnti[t1 * NN + tid] += a1;
        s_cnti[t2 * NN + tid] += a2;
        s_cnti[t3 * NN + tid] += a3;
        s_cnti[t4 * NN + tid] += a4;
        s_cnti[t5 * NN + tid] += a5;
        s_cnti[t6 * NN + tid] += a6;
        s_cnti[t7 * NN + tid] += a7;
    }
    __syncthreads();

    // convert to float and write out (coalesced float4)
    float* dst = g_cnt + (size_t)b * NVT * NN;
    for (int i = tid * 4; i < NVT * NN; i += 256 * 4) {
        float4 f;
        f.x = (float)s_cnti[i + 0];
        f.y = (float)s_cnti[i + 1];
        f.z = (float)s_cnti[i + 2];
        f.w = (float)s_cnti[i + 3];
        *(float4*)(dst + i) = f;
    }
}

// ---------- kernel B2: cnt@C GEMM + GRU + graph-sum + heads ----------
// smem: s_C 64K + s_cnt 32K + s_type 1K + s_hg 0.5K
#define SMEM_BYTES (65536 + 32768 + 1024 + 512)

__global__ __launch_bounds__(256, 2)
void dvae_main_kernel(const int* __restrict__ node_types,
                      const float* __restrict__ b_hh,
                      const float* __restrict__ W1, const float* __restrict__ b1,
                      const float* __restrict__ W2, const float* __restrict__ b2,
                      float* __restrict__ out) {
    extern __shared__ char smem[];
    float4* s_C    = (float4*)smem;                       // [32][128]
    float*  s_cnt  = (float*)(s_C + NVT * HS);            // [32][256]
    int*    s_type = (int*)(s_cnt + NVT * NN);            // [256]
    float*  s_hg   = (float*)(s_type + NN);               // [128]

    const int b   = blockIdx.x;
    const int tid = threadIdx.x;

    for (int i = tid; i < NVT * HS; i += 256) s_C[i] = g_C[i];
    s_type[tid] = node_types[b * NN + tid];
    {
        const float4* src = (const float4*)(g_cnt + (size_t)b * NVT * NN);
        float4* dst = (float4*)s_cnt;
        for (int i = tid; i < NVT * NN / 4; i += 256) dst[i] = src[i];
    }
    __syncthreads();

    const int hh  = tid & 127;   // h index
    const int grp = tid >> 7;    // v-subtile (0/1)
    const float bhr = b_hh[hh];
    const float bhz = b_hh[HS + hh];
    const float bhn = b_hh[2 * HS + hh];
    float hg = 0.f;

    for (int v0 = 0; v0 < NN; v0 += 2 * VT) {
        const int vb = v0 + grp * VT;
        float gr[VT], gz[VT], gn[VT], hp[VT];
        #pragma unroll
        for (int i = 0; i < VT; i++) { gr[i] = bhr; gz[i] = bhz; gn[i] = bhn; hp[i] = 0.f; }

        #pragma unroll 4
        for (int t = 0; t < NVT; t++) {
            const float4 co = s_C[t * HS + hh];             // LDS.128 (coalesced)
            const float mr = co.x, mz = co.y, mn = co.z, tb = co.w;
            const float4* cp = (const float4*)(s_cnt + t * NN + vb);
            #pragma unroll
            for (int i4 = 0; i4 < VT / 4; i4++) {
                float4 c4 = cp[i4];                          // broadcast LDS.128
                int i = i4 * 4;
                gr[i+0] += c4.x * mr; gz[i+0] += c4.x * mz; gn[i+0] += c4.x * mn; hp[i+0] += c4.x * tb;
                gr[i+1] += c4.y * mr; gz[i+1] += c4.y * mz; gn[i+1] += c4.y * mn; hp[i+1] += c4.y * tb;
                gr[i+2] += c4.z * mr; gz[i+2] += c4.z * mz; gn[i+2] += c4.z * mn; hp[i+2] += c4.z * tb;
                gr[i+3] += c4.w * mr; gz[i+3] += c4.w * mz; gn[i+3] += c4.w * mn; hp[i+3] += c4.w * tb;
            }
        }

        // GRU epilogue for this v-tile
        #pragma unroll
        for (int i = 0; i < VT; i++) {
            const int v  = vb + i;
            const int tv = s_type[v];
            const float gir = __ldg(&g_gi[tv * G3 + hh]);
            const float giz = __ldg(&g_gi[tv * G3 + HS + hh]);
            const float gin = __ldg(&g_gi[tv * G3 + 2 * HS + hh]);
            float r  = fast_sigmoid(gir + gr[i]);
            float z  = fast_sigmoid(giz + gz[i]);
            float nn = fast_tanh(gin + r * gn[i]);
            float Hv = (1.f - z) * nn + z * hp[i];
            if (v >= 1 && v < NN - 1) hg += Hv;   // graph state: v in [1, N-1)
        }
    }

    if (grp == 0) s_hg[hh] = hg;
    __syncthreads();
    if (grp == 1) s_hg[hh] += hg;
    __syncthreads();

    // ---- heads: mu (threads 0..63), logvar (threads 64..127) ----
    if (tid < 2 * NZ) {
        const int j = tid & (NZ - 1);
        const float* W  = (tid < NZ) ? W1 : W2;
        const float* bv = (tid < NZ) ? b1 : b2;
        float acc = bv[j];
        #pragma unroll 8
        for (int h = 0; h < HS; h++) acc += s_hg[h] * W[j * HS + h];
        out[((tid < NZ) ? 0 : BB * NZ) + b * NZ + j] = acc;
    }
}

// ---------- launch ----------
extern "C" void kernel_launch(void* const* d_in, const int* in_sizes, int n_in,
                              void* d_out, int out_size) {
    const int*   node_types = (const int*)  d_in[0];
    const int*   adj        = (const int*)  d_in[1];
    const float* W_ih       = (const float*)d_in[2];
    const float* W_hh       = (const float*)d_in[3];
    const float* b_ih       = (const float*)d_in[4];
    const float* b_hh       = (const float*)d_in[5];
    const float* Wg         = (const float*)d_in[6];
    const float* bg         = (const float*)d_in[7];
    const float* Wm         = (const float*)d_in[8];
    const float* W1         = (const float*)d_in[9];
    const float* b1         = (const float*)d_in[10];
    const float* W2         = (const float*)d_in[11];
    const float* b2         = (const float*)d_in[12];
    float* out = (float*)d_out;

    cudaFuncSetAttribute(dvae_main_kernel,
                         cudaFuncAttributeMaxDynamicSharedMemorySize, SMEM_BYTES);

    dvae_tables_kernel<<<NVT, G3>>>(W_ih, W_hh, b_ih, Wg, bg, Wm);
    dvae_hist_kernel<<<BB, 256>>>(node_types, adj);
    dvae_main_kernel<<<BB, 256, SMEM_BYTES>>>(node_types, b_hh,
                                              W1, b1, W2, b2, out);
}

// round 5
// speedup vs baseline: 2.2486x; 1.3734x over previous
#include <cuda_runtime.h>
#include <cuda_fp16.h>
#include <cstdint>

#define BB   512
#define NN   256
#define NVT  32
#define HS   128
#define G3   384
#define NZ   64

// ---------- device globals (no allocation allowed) ----------
// B fragments: [s(2)][nt(64)][k(2)][lane(32)][reg(2)][half(2)] bf16 = 64 KB
__device__ uint4 g_Bf4[4096];
// gi table, fp16, layout [c(3)][h(128)][t(32)] = 24 KB (b_hh baked into r,z)
__device__ uint4 g_giT4[1536];
// A fragments per batch: [mt(16)][k(2)][lane(32)][reg(4)] bf16x2 = 16 KB/batch
__device__ uint4 g_Af4[(size_t)BB * 1024];

__device__ __forceinline__ float fast_sigmoid(float x) {
    return __fdividef(1.f, 1.f + __expf(-x));
}
__device__ __forceinline__ float fast_tanh(float x) {
    float e = __expf(2.f * x);
    return 1.f - __fdividef(2.f, e + 1.f);
}
__device__ __forceinline__ uint32_t f2bf(float x) {   // rn bf16 bits
    uint32_t u = __float_as_uint(x);
    u += 0x7fff + ((u >> 16) & 1);
    return u >> 16;
}
__device__ __forceinline__ void mma_bf16(float* c, const uint32_t* a,
                                         uint32_t b0, uint32_t b1) {
    asm volatile(
        "mma.sync.aligned.m16n8k16.row.col.f32.bf16.bf16.f32 "
        "{%0,%1,%2,%3}, {%4,%5,%6,%7}, {%8,%9}, {%0,%1,%2,%3};"
        : "+f"(c[0]), "+f"(c[1]), "+f"(c[2]), "+f"(c[3])
        : "r"(a[0]), "r"(a[1]), "r"(a[2]), "r"(a[3]), "r"(b0), "r"(b1));
}

// ---------- kernel A: build tables in fragment layout ----------
__global__ void dvae_tables_kernel(const float* __restrict__ W_ih,
                                   const float* __restrict__ W_hh,
                                   const float* __restrict__ b_ih,
                                   const float* __restrict__ b_hh,
                                   const float* __restrict__ Wg,
                                   const float* __restrict__ bg,
                                   const float* __restrict__ Wm) {
    __shared__ float s_tbl[HS];
    const int t = blockIdx.x;      // 0..31 (type = K index)
    const int g = threadIdx.x;     // 0..383
    if (g < HS) {
        float x  = Wg[g * NVT + t] + bg[g];
        float sg = __fdividef(1.f, 1.f + __expf(-x));
        s_tbl[g] = sg * Wm[g * NVT + t];
    }
    __syncthreads();

    const float4* w4 = (const float4*)(W_hh + g * HS);
    const float4* t4 = (const float4*)s_tbl;
    float a0 = 0.f, a1 = 0.f, a2 = 0.f, a3 = 0.f;
    #pragma unroll
    for (int i = 0; i < 32; i += 4) {
        float4 w0 = w4[i], w1 = w4[i+1], w2 = w4[i+2], w3 = w4[i+3];
        float4 x0 = t4[i], x1 = t4[i+1], x2 = t4[i+2], x3 = t4[i+3];
        a0 += w0.x*x0.x + w0.y*x0.y + w0.z*x0.z + w0.w*x0.w;
        a1 += w1.x*x1.x + w1.y*x1.y + w1.z*x1.z + w1.w*x1.w;
        a2 += w2.x*x2.x + w2.y*x2.y + w2.z*x2.z + w2.w*x2.w;
        a3 += w3.x*x3.x + w3.y*x3.y + w3.z*x3.z + w3.w*x3.w;
    }
    float acc = (a0 + a1) + (a2 + a3);

    unsigned short* B = (unsigned short*)g_Bf4;
    // store hi/lo bf16 of val at column j, k-row t
    auto storeB = [&](int j, float val) {
        int nt = j >> 3, nin = j & 7;
        int k = t >> 4, kk = t & 15;
        int tig = (kk & 7) >> 1, half = kk & 1, reg = kk >> 3;
        int lane = nin * 4 + tig;
        int base = (((nt * 2 + k) * 32 + lane) * 2 + reg) * 2 + half;
        uint32_t hb = f2bf(val);
        float lo = val - __uint_as_float(hb << 16);
        B[base]         = (unsigned short)hb;
        B[16384 + base] = (unsigned short)f2bf(lo);
    };
    // M columns: j = h*4 + c  (c: 0=r, 1=z, 2=n)
    storeB((g & 127) * 4 + (g >> 7), acc);
    // tbl columns: j = h*4 + 3
    if (g < HS) storeB(g * 4 + 3, s_tbl[g]);

    // gi table fp16: [c][h][t], b_hh baked into r,z
    {
        __half* GI = (__half*)g_giT4;
        int c = g >> 7, h = g & 127;
        float val = W_ih[g * NVT + t] + b_ih[g] + ((g < 256) ? b_hh[g] : 0.f);
        GI[(c * 128 + h) * 32 + t] = __float2half_rn(val);
    }
}

// ---------- kernel B1: histogram -> A fragments (bf16) ----------
__global__ __launch_bounds__(256)
void dvae_hist_kernel(const int* __restrict__ node_types,
                      const int* __restrict__ adj) {
    __shared__ int s_cnti[NVT * NN];
    __shared__ int s_type[NN];

    const int b   = blockIdx.x;
    const int tid = threadIdx.x;

    s_type[tid] = node_types[b * NN + tid];
    for (int i = tid; i < NVT * NN; i += 256) s_cnti[i] = 0;
    __syncthreads();

    const int* arow = adj + (size_t)b * NN * NN + tid;
    #pragma unroll 1
    for (int u0 = 0; u0 < NN; u0 += 8) {
        int a0 = __ldg(arow + (u0 + 0) * NN);
        int a1 = __ldg(arow + (u0 + 1) * NN);
        int a2 = __ldg(arow + (u0 + 2) * NN);
        int a3 = __ldg(arow + (u0 + 3) * NN);
        int a4 = __ldg(arow + (u0 + 4) * NN);
        int a5 = __ldg(arow + (u0 + 5) * NN);
        int a6 = __ldg(arow + (u0 + 6) * NN);
        int a7 = __ldg(arow + (u0 + 7) * NN);
        s_cnti[s_type[u0 + 0] * NN + tid] += a0;
        s_cnti[s_type[u0 + 1] * NN + tid] += a1;
        s_cnti[s_type[u0 + 2] * NN + tid] += a2;
        s_cnti[s_type[u0 + 3] * NN + tid] += a3;
        s_cnti[s_type[u0 + 4] * NN + tid] += a4;
        s_cnti[s_type[u0 + 5] * NN + tid] += a5;
        s_cnti[s_type[u0 + 6] * NN + tid] += a6;
        s_cnti[s_type[u0 + 7] * NN + tid] += a7;
    }
    __syncthreads();

    // write A fragments: counts are exact in bf16 (<= 255)
    uint32_t* dst = (uint32_t*)g_Af4 + (size_t)b * 4096;
    for (int lin = tid; lin < 4096; lin += 256) {
        int reg  = lin & 3;
        int lane = (lin >> 2) & 31;
        int k    = (lin >> 7) & 1;
        int mt   = lin >> 8;
        int g    = lane >> 2, tig = lane & 3;
        int v    = mt * 16 + (reg & 1) * 8 + g;
        int t0   = k * 16 + (reg >> 1) * 8 + tig * 2;
        uint32_t u0 = __float_as_uint((float)s_cnti[t0 * NN + v]) >> 16;
        uint32_t u1 = __float_as_uint((float)s_cnti[(t0 + 1) * NN + v]) >> 16;
        dst[lin] = u0 | (u1 << 16);
    }
}

// ---------- kernel B2: bf16 mma GEMM + GRU + heads ----------
// smem: sB 64K + pgi 24K + pbhn 512 + spart 4096 + phg 512 = 93.0 KB
#define SMEM_DYN (65536 + 24576 + 512 + 4096 + 512)

__global__ __launch_bounds__(256, 2)
void dvae_main_kernel(const int* __restrict__ node_types,
                      const float* __restrict__ b_hh,
                      const float* __restrict__ W1, const float* __restrict__ b1,
                      const float* __restrict__ W2, const float* __restrict__ b2,
                      float* __restrict__ out) {
    extern __shared__ char smem[];
    uint32_t* sB    = (uint32_t*)smem;                  // 16384 u32
    __half*   pgi   = (__half*)(smem + 65536);          // 12288 halves
    float*    pbhn  = (float*)(smem + 65536 + 24576);   // [128]
    float*    spart = pbhn + 128;                       // [8][128]
    float*    phg   = spart + 8 * 128;                  // [128]

    const int b    = blockIdx.x;
    const int tid  = threadIdx.x;
    const int wid  = tid >> 5;
    const int lane = tid & 31;

    // ---- stage B frags + gi (uint4 copies) ----
    {
        uint4* d = (uint4*)sB;
        for (int i = tid; i < 4096; i += 256) d[i] = g_Bf4[i];
        uint4* d2 = (uint4*)pgi;
        for (int i = tid; i < 1536; i += 256) d2[i] = g_giT4[i];
    }
    if (tid < 128) pbhn[tid] = b_hh[256 + tid];
    __syncthreads();

    // ---- A fragments: 2 m-tiles per warp, 2 k-steps ----
    uint4 areg[2][2];
    #pragma unroll
    for (int mt2 = 0; mt2 < 2; mt2++)
        #pragma unroll
        for (int k = 0; k < 2; k++)
            areg[mt2][k] = g_Af4[(size_t)b * 1024 +
                                 (((wid * 2 + mt2) * 2 + k) * 32 + lane)];

    const int g    = lane >> 2;
    const int tig  = lane & 3;
    const int odd  = tig & 1;
    const int hbit = tig >> 1;
    const int rowoff = g + (odd << 3);

    int   tv[2];
    bool  excl[2];
    #pragma unroll
    for (int mt2 = 0; mt2 < 2; mt2++) {
        int v = (wid * 2 + mt2) * 16 + rowoff;
        tv[mt2]   = node_types[b * NN + v];
        excl[mt2] = (v == 0) || (v == NN - 1);
    }

    // ---- GEMM + fused epilogue over 64 n-tiles ----
    #pragma unroll 2
    for (int nt = 0; nt < 64; nt++) {
        float cc[2][4] = {{0.f,0.f,0.f,0.f},{0.f,0.f,0.f,0.f}};
        #pragma unroll
        for (int s = 0; s < 2; s++)
            #pragma unroll
            for (int k = 0; k < 2; k++) {
                uint2 bb = *(const uint2*)(sB +
                    (((s * 64 + nt) * 2 + k) * 32 + lane) * 2);
                mma_bf16(cc[0], (const uint32_t*)&areg[0][k], bb.x, bb.y);
                mma_bf16(cc[1], (const uint32_t*)&areg[1][k], bb.x, bb.y);
            }

        const int h = nt * 2 + hbit;
        const float bhn = pbhn[h];
        float acc = 0.f;
        #pragma unroll
        for (int mt2 = 0; mt2 < 2; mt2++) {
            float* c = cc[mt2];
            // exchange between (r,z) lanes and (n,tb) lanes
            float r1 = __shfl_xor_sync(0xffffffffu, odd ? c[0] : c[2], 1);
            float r2 = __shfl_xor_sync(0xffffffffu, odd ? c[1] : c[3], 1);
            float rin  = odd ? r1 : c[0];
            float zin  = odd ? r2 : c[1];
            float nin  = odd ? c[2] : r1;
            float hpre = odd ? c[3] : r2;
            int ti = tv[mt2];
            float gi_r = __half2float(pgi[(      h) * 32 + ti]);
            float gi_z = __half2float(pgi[(128 + h) * 32 + ti]);
            float gi_n = __half2float(pgi[(256 + h) * 32 + ti]);
            float r  = fast_sigmoid(gi_r + rin);
            float z  = fast_sigmoid(gi_z + zin);
            float nn = fast_tanh(gi_n + r * (nin + bhn));
            float Hv = (1.f - z) * nn + z * hpre;
            if (!excl[mt2]) acc += Hv;
        }
        // reduce the 16 lanes sharing this h (masks avoid bit 1<<1)
        acc += __shfl_xor_sync(0xffffffffu, acc, 1);
        acc += __shfl_xor_sync(0xffffffffu, acc, 4);
        acc += __shfl_xor_sync(0xffffffffu, acc, 8);
        acc += __shfl_xor_sync(0xffffffffu, acc, 16);
        if ((lane & ~2u) == 0)            // lanes 0 (h even) and 2 (h odd)
            spart[wid * 128 + nt * 2 + (lane >> 1)] = acc;
    }
    __syncthreads();

    // ---- reduce partials, heads ----
    if (tid < HS) {
        float s = 0.f;
        #pragma unroll
        for (int w = 0; w < 8; w++) s += spart[w * 128 + tid];
        phg[tid] = s;
    }
    __syncthreads();

    if (tid < 2 * NZ) {
        const int j = tid & (NZ - 1);
        const float* W  = (tid < NZ) ? W1 : W2;
        const float* bv = (tid < NZ) ? b1 : b2;
        float a0 = bv[j], a1 = 0.f, a2 = 0.f, a3 = 0.f;
        #pragma unroll
        for (int h = 0; h < HS; h += 4) {
            a0 += phg[h + 0] * W[j * HS + h + 0];
            a1 += phg[h + 1] * W[j * HS + h + 1];
            a2 += phg[h + 2] * W[j * HS + h + 2];
            a3 += phg[h + 3] * W[j * HS + h + 3];
        }
        out[((tid < NZ) ? 0 : BB * NZ) + b * NZ + j] = (a0 + a1) + (a2 + a3);
    }
}

// ---------- launch ----------
extern "C" void kernel_launch(void* const* d_in, const int* in_sizes, int n_in,
                              void* d_out, int out_size) {
    const int*   node_types = (const int*)  d_in[0];
    const int*   adj        = (const int*)  d_in[1];
    const float* W_ih       = (const float*)d_in[2];
    const float* W_hh       = (const float*)d_in[3];
    const float* b_ih       = (const float*)d_in[4];
    const float* b_hh       = (const float*)d_in[5];
    const float* Wg         = (const float*)d_in[6];
    const float* bg         = (const float*)d_in[7];
    const float* Wm         = (const float*)d_in[8];
    const float* W1         = (const float*)d_in[9];
    const float* b1         = (const float*)d_in[10];
    const float* W2         = (const float*)d_in[11];
    const float* b2         = (const float*)d_in[12];
    float* out = (float*)d_out;

    cudaFuncSetAttribute(dvae_main_kernel,
                         cudaFuncAttributeMaxDynamicSharedMemorySize, SMEM_DYN);

    dvae_tables_kernel<<<NVT, G3>>>(W_ih, W_hh, b_ih, b_hh, Wg, bg, Wm);
    dvae_hist_kernel<<<BB, 256>>>(node_types, adj);
    dvae_main_kernel<<<BB, 256, SMEM_DYN>>>(node_types, b_hh,
                                            W1, b1, W2, b2, out);
}